// round 8
// baseline (speedup 1.0000x reference)
#include <cuda_runtime.h>
#include <cuda_fp16.h>
#include <cstdint>
#include <math.h>

#define NN 8192
#define DD 128
#define BM 128
#define BN 128
#define BK 32
#define STR 40            // smem K-stride in halves (80 B): 16B-aligned rows, 5*row%8 -> conflict-free ldmatrix
#define TILES 64
#define NACT (TILES*(TILES+1)/2)   // 2080 upper-triangle blocks
#define NPAD 2304                  // 9*256, zero-padded partial array

__device__ __half X16[NN * DD];   // fp16 copy of inputs (2 MB)
__device__ float  g_partial[NPAD];
__device__ int    g_count;        // zero-init; last active block resets

__device__ __forceinline__ uint32_t smem_u32(const void* p) {
    uint32_t a;
    asm("{ .reg .u64 t; cvta.to.shared.u64 t, %1; cvt.u32.u64 %0, t; }" : "=r"(a) : "l"(p));
    return a;
}

__device__ __forceinline__ void cp_async16(uint32_t s, const void* g) {
    asm volatile("cp.async.cg.shared.global [%0], [%1], 16;" :: "r"(s), "l"(g) : "memory");
}
#define CP_COMMIT() asm volatile("cp.async.commit_group;" ::: "memory")
#define CP_WAIT(n)  asm volatile("cp.async.wait_group %0;" :: "n"(n) : "memory")

__device__ __forceinline__ void ldsm_x4(uint32_t& r0, uint32_t& r1, uint32_t& r2, uint32_t& r3,
                                        uint32_t addr) {
    asm volatile("ldmatrix.sync.aligned.m8n8.x4.shared.b16 {%0,%1,%2,%3}, [%4];"
                 : "=r"(r0), "=r"(r1), "=r"(r2), "=r"(r3) : "r"(addr));
}

__device__ __forceinline__ void mma16816(float* c, uint32_t a0, uint32_t a1, uint32_t a2,
                                         uint32_t a3, uint32_t b0, uint32_t b1) {
    asm volatile("mma.sync.aligned.m16n8k16.row.col.f32.f16.f16.f32 "
                 "{%0,%1,%2,%3}, {%4,%5,%6,%7}, {%8,%9}, {%0,%1,%2,%3};"
                 : "+f"(c[0]), "+f"(c[1]), "+f"(c[2]), "+f"(c[3])
                 : "r"(a0), "r"(a1), "r"(a2), "r"(a3), "r"(b0), "r"(b1));
}

// ---------------- kernel 1: fp32 -> fp16 convert ----------------
__global__ void convert_kernel(const float* __restrict__ X) {
    int idx = (blockIdx.x * blockDim.x + threadIdx.x) * 4;
    float4 v = *(const float4*)&X[idx];
    __half2* o = (__half2*)&X16[idx];
    o[0] = __floats2half2_rn(v.x, v.y);
    o[1] = __floats2half2_rn(v.z, v.w);
}

// triangle row offset: first linear index of row r
__device__ __forceinline__ int tri_off(int r) { return r * TILES - (r * (r - 1)) / 2; }

// ---------------- kernel 2: fused HMMA GEMM + mask + reduce (upper triangle) ----------------
__global__ __launch_bounds__(256, 2)
void sim_loss_mma(const float* __restrict__ margin,
                  const int* __restrict__ tgt,
                  float* __restrict__ out) {
    // recover (by, bx) from linear upper-triangle index
    const int b = blockIdx.x;
    int by = (int)((129.0 - sqrt(16641.0 - 8.0 * (double)b)) * 0.5);
    while (tri_off(by + 1) <= b) ++by;
    while (tri_off(by) > b) --by;
    const int bx = by + (b - tri_off(by));
    const bool diag = (by == bx);

    __shared__ __half As[2][BM * STR];
    __shared__ __half Bs[2][BN * STR];
    __shared__ int   cs[BN];
    __shared__ float cm[BN];
    __shared__ int   rt[BM];
    __shared__ float rm[BM];
    __shared__ float red[8];
    __shared__ int   flag;

    const int tid  = threadIdx.x;
    const int lane = tid & 31;
    const int wid  = tid >> 5;
    const int wm   = wid & 1;
    const int wn   = wid >> 1;
    const int rowBase = by * BM;
    const int colBase = bx * BN;

    const uint32_t sAb[2] = { smem_u32(As[0]), smem_u32(As[1]) };
    const uint32_t sBb[2] = { smem_u32(Bs[0]), smem_u32(Bs[1]) };

    // per-thread cp.async mapping: 4 x 16B per chunk (2 tiles x 512 ops / 256 thr)
    auto prefetch = [&](int kc, int buf) {
#pragma unroll
        for (int p = 0; p < 4; p++) {
            int id   = tid + p * 256;
            int tile = id >> 9;
            int e    = id & 511;
            int row  = e >> 2;
            int ch   = e & 3;
            const __half* src = &X16[(size_t)((tile ? colBase : rowBase) + row) * DD + kc * BK + ch * 8];
            uint32_t dst = (tile ? sBb[buf] : sAb[buf]) + (uint32_t)(row * STR + ch * 8) * 2;
            cp_async16(dst, src);
        }
        CP_COMMIT();
    };

    float acc[4][4][4];
#pragma unroll
    for (int mi = 0; mi < 4; mi++)
#pragma unroll
        for (int ni = 0; ni < 4; ni++)
#pragma unroll
            for (int q = 0; q < 4; q++) acc[mi][ni][q] = 0.0f;

    prefetch(0, 0);

    if (tid < 128) {
        cs[tid] = tgt[colBase + tid];
        cm[tid] = margin[colBase + tid];
        rt[tid] = tgt[rowBase + tid];
        rm[tid] = margin[rowBase + tid];
    }

    const int lrow = lane & 15;
    const int lchk = lane >> 4;

#pragma unroll
    for (int kc = 0; kc < DD / BK; kc++) {
        const int buf = kc & 1;
        if (kc + 1 < DD / BK) {
            prefetch(kc + 1, buf ^ 1);
            CP_WAIT(1);           // chunk kc has landed
        } else {
            CP_WAIT(0);
        }
        __syncthreads();

#pragma unroll
        for (int ks = 0; ks < BK / 16; ks++) {
            uint32_t a[4][4];
#pragma unroll
            for (int mi = 0; mi < 4; mi++) {
                uint32_t addr = sAb[buf] + (uint32_t)((wm * 64 + mi * 16 + lrow) * STR + ks * 16 + lchk * 8) * 2;
                ldsm_x4(a[mi][0], a[mi][1], a[mi][2], a[mi][3], addr);
            }
            uint32_t bfr[2][4];
#pragma unroll
            for (int nb = 0; nb < 2; nb++) {
                uint32_t addr = sBb[buf] + (uint32_t)((wn * 32 + nb * 16 + lrow) * STR + ks * 16 + lchk * 8) * 2;
                ldsm_x4(bfr[nb][0], bfr[nb][1], bfr[nb][2], bfr[nb][3], addr);
            }
#pragma unroll
            for (int mi = 0; mi < 4; mi++)
#pragma unroll
                for (int ni = 0; ni < 4; ni++)
                    mma16816(acc[mi][ni], a[mi][0], a[mi][1], a[mi][2], a[mi][3],
                             bfr[ni >> 1][ni & 1], bfr[ni >> 1][2 + (ni & 1)]);
        }
        __syncthreads();          // buf free for prefetch kc+2
    }

    // ---- branchless epilogue ----
    // fragment: c0:(r,c) c1:(r,c+1) c2:(r+8,c) c3:(r+8,c+1); r=lane/4, c=2*(lane&3)
    const int r0l = (lane >> 2);
    const int c0l = (lane & 3) * 2;
    float local = 0.0f;

#pragma unroll
    for (int mi = 0; mi < 4; mi++) {
        const int rA = wm * 64 + mi * 16 + r0l;
        const int rB = rA + 8;
        const int   trA = rt[rA], trB = rt[rB];
        const float mgA = rm[rA], mgB = rm[rB];
#pragma unroll
        for (int ni = 0; ni < 4; ni++) {
            const int c0 = wn * 32 + ni * 8 + c0l;
            const int   tc0 = cs[c0], tc1 = cs[c0 + 1];
            const float mc0 = cm[c0], mc1 = cm[c0 + 1];
            float s, pos, neg;
            if (diag) {
                s = acc[mi][ni][0];
                pos = fmaxf(1.0f - s, 0.0f);
                neg = (s > mgA) ? s : 0.0f;
                local += (trA == tc0) ? pos : neg;
                s = acc[mi][ni][1];
                pos = fmaxf(1.0f - s, 0.0f);
                neg = (s > mgA) ? s : 0.0f;
                local += (trA == tc1) ? pos : neg;
                s = acc[mi][ni][2];
                pos = fmaxf(1.0f - s, 0.0f);
                neg = (s > mgB) ? s : 0.0f;
                local += (trB == tc0) ? pos : neg;
                s = acc[mi][ni][3];
                pos = fmaxf(1.0f - s, 0.0f);
                neg = (s > mgB) ? s : 0.0f;
                local += (trB == tc1) ? pos : neg;
            } else {
                s = acc[mi][ni][0];
                pos = 2.0f * fmaxf(1.0f - s, 0.0f);
                neg = ((s > mgA) ? s : 0.0f) + ((s > mc0) ? s : 0.0f);
                local += (trA == tc0) ? pos : neg;
                s = acc[mi][ni][1];
                pos = 2.0f * fmaxf(1.0f - s, 0.0f);
                neg = ((s > mgA) ? s : 0.0f) + ((s > mc1) ? s : 0.0f);
                local += (trA == tc1) ? pos : neg;
                s = acc[mi][ni][2];
                pos = 2.0f * fmaxf(1.0f - s, 0.0f);
                neg = ((s > mgB) ? s : 0.0f) + ((s > mc0) ? s : 0.0f);
                local += (trB == tc0) ? pos : neg;
                s = acc[mi][ni][3];
                pos = 2.0f * fmaxf(1.0f - s, 0.0f);
                neg = ((s > mgB) ? s : 0.0f) + ((s > mc1) ? s : 0.0f);
                local += (trB == tc1) ? pos : neg;
            }
        }
    }

    // ---- block reduce ----
#pragma unroll
    for (int off = 16; off > 0; off >>= 1)
        local += __shfl_xor_sync(0xFFFFFFFFu, local, off);
    if (lane == 0) red[wid] = local;
    __syncthreads();

    if (tid == 0) {
        float s = 0.0f;
#pragma unroll
        for (int w = 0; w < 8; w++) s += red[w];
        g_partial[b] = s;
    }

    // ---- deterministic last-block final reduce (g_partial[2080..2303] stay 0) ----
    __threadfence();
    __syncthreads();
    if (tid == 0) flag = (atomicAdd(&g_count, 1) == NACT - 1) ? 1 : 0;
    __syncthreads();
    if (flag) {
        float v = 0.0f;
#pragma unroll
        for (int p = 0; p < NPAD / 256; p++)
            v += g_partial[tid + p * 256];
#pragma unroll
        for (int off = 16; off > 0; off >>= 1)
            v += __shfl_xor_sync(0xFFFFFFFFu, v, off);
        if (lane == 0) red[wid] = v;
        __syncthreads();
        if (tid == 0) {
            float s = 0.0f;
#pragma unroll
            for (int w = 0; w < 8; w++) s += red[w];
            out[0] = s / (float)NN;
            g_count = 0;   // restore for next graph replay
        }
    }
}

// ---------------- launcher ----------------
extern "C" void kernel_launch(void* const* d_in, const int* in_sizes, int n_in,
                              void* d_out, int out_size) {
    const float* X      = (const float*)d_in[0];
    const float* margin = (const float*)d_in[1];
    const int*   tgt    = (const int*)d_in[2];
    float*       out    = (float*)d_out;

    convert_kernel<<<NN * DD / 4 / 256, 256>>>(X);
    sim_loss_mma<<<NACT, 256>>>(margin, tgt, out);
}